// round 15
// baseline (speedup 1.0000x reference)
#include <cuda_runtime.h>

// ============================================================================
// KmeansAssigner: out[n] = argmin_k ( ||c_k||^2 - 2 * x_n . c_k )
// N=131072 C=512 K=2048.
//
// Round 15: R14 regression root-caused. The quad merge interleaved
// shfl+insert, reading partner state mid-mutation -> duplicate keys ->
// v2-v1==0 -> ~all rows flagged -> FLAG_CAP overflow -> near-ties left
// unrefined (rel_err 6.2e-3). Fix: fetch-then-insert merge (R13 pattern,
// duplicate-free by disjoint column sets) + FLAG_CAP = N.
// ============================================================================

#define C_DIM 512
#define N_CAP 131072
#define K_CAP 2048
#define FLAG_CAP 131072
#define FLAG_THRESH 6.0f

#define SMEM_A_BYTES 65536             // 128 rows x 512B (int8)
#define SMEM_B_BYTES 16384             // 128 cols x 128B (int8 k-chunk)
#define SMEM_SX_OFF  (SMEM_A_BYTES + 2 * SMEM_B_BYTES)
#define SMEM_TOTAL   (SMEM_SX_OFF + 512)
#define NTHREADS 512

__device__ signed char g_X8[(size_t)N_CAP * C_DIM];
__device__ signed char g_C8[(size_t)K_CAP * C_DIM];
__device__ float g_sx[N_CAP];
__device__ float g_sc[K_CAP];
__device__ float g_c2[K_CAP];
__device__ int   g_flag_count;
__device__ int   g_flag_rows[FLAG_CAP];
__device__ int4  g_flag_cand_lo[FLAG_CAP];
__device__ int4  g_flag_cand_hi[FLAG_CAP];

// ---------------------------------------------------------------------------
__device__ __forceinline__ unsigned smem_u32(const void* p) {
    unsigned a;
    asm("{ .reg .u64 t; cvta.to.shared.u64 t, %1; cvt.u32.u64 %0, t; }"
        : "=r"(a) : "l"(p));
    return a;
}
#define CP16(dst, src)                                                         \
    asm volatile("cp.async.cg.shared.global [%0], [%1], 16;"                   \
                 :: "r"(dst), "l"(src) : "memory")
#define CP_COMMIT() asm volatile("cp.async.commit_group;" ::: "memory")
#define CP_WAIT0()  asm volatile("cp.async.wait_group 0;" ::: "memory")
#define LDSM_X4(R, addr)                                                       \
    asm volatile("ldmatrix.sync.aligned.m8n8.x4.shared.b16 {%0,%1,%2,%3}, [%4];" \
                 : "=r"((R)[0]), "=r"((R)[1]), "=r"((R)[2]), "=r"((R)[3])      \
                 : "r"(addr))
#define MMA_S8(Cc, A, B0, B1)                                                  \
    asm volatile("mma.sync.aligned.m16n8k32.row.col.s32.s8.s8.s32 "            \
                 "{%0,%1,%2,%3}, {%4,%5,%6,%7}, {%8,%9}, {%0,%1,%2,%3};"       \
                 : "+r"((Cc)[0]), "+r"((Cc)[1]), "+r"((Cc)[2]), "+r"((Cc)[3])  \
                 : "r"((A)[0]), "r"((A)[1]), "r"((A)[2]), "r"((A)[3]),         \
                   "r"(B0), "r"(B1))

// A smem: [128 rows][512B], XOR swizzle inside 128B blocks (kb mult of 16).
__device__ __forceinline__ unsigned a_off(int row, int kb) {
    return (unsigned)(row * 512 + (kb & ~127) +
                      ((((kb >> 4) & 7) ^ (row & 7)) << 4));
}
// B smem: [128 cols][128B] (one 128-elem int8 k-chunk per col), XOR swizzle.
__device__ __forceinline__ unsigned b_off(int col, int kb) {
    return (unsigned)(col * 128 + ((((kb >> 4) & 7) ^ (col & 7)) << 4));
}

// order-preserving float->uint, low 11 bits replaced by col (tiebreak low col)
__device__ __forceinline__ unsigned packkey(float s, int col) {
    unsigned u = __float_as_uint(s);
    u ^= (unsigned)(((int)u >> 31)) | 0x80000000u;
    return (u & ~2047u) | (unsigned)col;
}
__device__ __forceinline__ float unpackv(unsigned key) {
    unsigned u = (key & 0x80000000u) ? (key ^ 0x80000000u) : ~key;
    return __uint_as_float(u);
}
// sorted insert into ascending t[0..7]
__device__ __forceinline__ void ins8(unsigned* t, unsigned k) {
    if (k < t[7]) {
        t[7] = k;
#pragma unroll
        for (int j = 7; j > 0; j--) {
            unsigned a = t[j - 1], b = t[j];
            t[j - 1] = a < b ? a : b;
            t[j]     = a < b ? b : a;
        }
    }
}
__device__ __forceinline__ int q8(float v, float inv) {
    int q = __float2int_rn(v * inv);
    return q < -127 ? -127 : (q > 127 ? 127 : q);
}
__device__ __forceinline__ unsigned pack4(const float* v, float inv) {
    return (unsigned)(q8(v[0], inv) & 255) |
           ((unsigned)(q8(v[1], inv) & 255) << 8) |
           ((unsigned)(q8(v[2], inv) & 255) << 16) |
           ((unsigned)(q8(v[3], inv) & 255) << 24);
}

// --- quantize X rows to int8 (per-row scale); reset flag counter -----------
__global__ void convx8_kernel(const float* __restrict__ X, int N) {
    if (blockIdx.x == 0 && threadIdx.x == 0) g_flag_count = 0;
    int row = (int)blockIdx.x * 8 + (threadIdx.x >> 5);
    int lane = threadIdx.x & 31;
    if (row >= N) return;
    const float4* src = (const float4*)(X + (size_t)row * C_DIM) + lane * 4;
    float4 v[4];
    float mx = 0.0f;
#pragma unroll
    for (int i = 0; i < 4; i++) {
        v[i] = src[i];
        mx = fmaxf(mx, fmaxf(fmaxf(fabsf(v[i].x), fabsf(v[i].y)),
                             fmaxf(fabsf(v[i].z), fabsf(v[i].w))));
    }
#pragma unroll
    for (int o = 16; o > 0; o >>= 1)
        mx = fmaxf(mx, __shfl_xor_sync(0xFFFFFFFFu, mx, o));
    mx = fmaxf(mx, 1e-20f);
    float inv = 127.0f / mx;
    int4 p;
    p.x = (int)pack4(&v[0].x, inv);
    p.y = (int)pack4(&v[1].x, inv);
    p.z = (int)pack4(&v[2].x, inv);
    p.w = (int)pack4(&v[3].x, inv);
    ((int4*)(g_X8 + (size_t)row * C_DIM))[lane] = p;
    if (lane == 0) g_sx[row] = mx / 127.0f;
}

// --- centroid: exact ||c||^2 (fp32) + int8 quantization, warp per row ------
__global__ void c2s_kernel(const float* __restrict__ cent, int K) {
    int row = (int)((blockIdx.x * blockDim.x + threadIdx.x) >> 5);
    int lane = threadIdx.x & 31;
    if (row >= K || row >= K_CAP) return;
    const float4* src = (const float4*)(cent + (size_t)row * C_DIM) + lane * 4;
    float4 v[4];
    float mx = 0.0f, s2 = 0.0f;
#pragma unroll
    for (int i = 0; i < 4; i++) {
        v[i] = src[i];
        mx = fmaxf(mx, fmaxf(fmaxf(fabsf(v[i].x), fabsf(v[i].y)),
                             fmaxf(fabsf(v[i].z), fabsf(v[i].w))));
        s2 = fmaf(v[i].x, v[i].x, s2); s2 = fmaf(v[i].y, v[i].y, s2);
        s2 = fmaf(v[i].z, v[i].z, s2); s2 = fmaf(v[i].w, v[i].w, s2);
    }
#pragma unroll
    for (int o = 16; o > 0; o >>= 1) {
        mx = fmaxf(mx, __shfl_xor_sync(0xFFFFFFFFu, mx, o));
        s2 += __shfl_xor_sync(0xFFFFFFFFu, s2, o);
    }
    mx = fmaxf(mx, 1e-20f);
    float inv = 127.0f / mx;
    int4 p;
    p.x = (int)pack4(&v[0].x, inv);
    p.y = (int)pack4(&v[1].x, inv);
    p.z = (int)pack4(&v[2].x, inv);
    p.w = (int)pack4(&v[3].x, inv);
    ((int4*)(g_C8 + (size_t)row * C_DIM))[lane] = p;
    if (lane == 0) { g_sc[row] = mx / 127.0f; g_c2[row] = s2; }
}

// --- B chunk staging (16KB: 128 cols x 128 int8 k) -------------------------
__device__ __forceinline__ void stage_B(unsigned sb, int T) {
    int nc = T >> 2, kk = T & 3, buf = T & 1;
    int tid = threadIdx.x;
    const signed char* srcb = g_C8 + ((size_t)nc * 128) * C_DIM + kk * 128;
    unsigned base = sb + SMEM_A_BYTES + (unsigned)buf * SMEM_B_BYTES;
#pragma unroll
    for (int i = 0; i < 2; i++) {
        int idx = tid + i * NTHREADS;         // 16B granule 0..1023
        int col = idx >> 3, u = idx & 7;
        unsigned dst = base + (unsigned)(col * 128 + ((u ^ (col & 7)) << 4));
        const void* s = srcb + (size_t)col * C_DIM + u * 16;
        CP16(dst, s);
    }
}

// --- main: int8 mma.sync GEMM + fused top-8 argmin -------------------------
__global__ void __launch_bounds__(NTHREADS, 1)
assign_mma(float* __restrict__ out, int K) {
    extern __shared__ char smem[];
    unsigned sb = smem_u32(smem);
    const int tid = threadIdx.x, lane = tid & 31, wid = tid >> 5;
    const int wr = wid >> 2, wc = wid & 3;   // warp grid 4 (rows) x 4 (cols)
    const int blockRow = (int)blockIdx.x * 128;
    float* sxs = (float*)(smem + SMEM_SX_OFF);

    // prologue: stage A tile (128 rows x 512 int8 = 64KB) + sx + B chunk 0
    {
        const signed char* src = g_X8 + (size_t)blockRow * C_DIM;
#pragma unroll
        for (int i = 0; i < 8; i++) {
            int idx = tid + i * NTHREADS;     // 16B granule 0..4095
            int row = idx >> 5, u = idx & 31;
            unsigned dst = sb + a_off(row, u * 16);
            const void* s = src + (size_t)row * C_DIM + u * 16;
            CP16(dst, s);
        }
    }
    if (tid < 128) sxs[tid] = g_sx[blockRow + tid];
    stage_B(sb, 0);
    CP_COMMIT();
    CP_WAIT0();
    __syncthreads();

    // per-thread row scales (rows: wr*32 + mt*16 + h*8 + lane/4)
    float sxr[4];
#pragma unroll
    for (int r = 0; r < 4; r++)
        sxr[r] = sxs[wr * 32 + (r >> 1) * 16 + (r & 1) * 8 + (lane >> 2)];

    int      acc[2][4][4];                   // warp tile 32 rows x 32 cols
    unsigned t8[4][8];
#pragma unroll
    for (int r = 0; r < 4; r++)
#pragma unroll
        for (int j = 0; j < 8; j++) t8[r][j] = 0xFFFFFFFFu;

    const int NT = (K / 128) * 4;            // 4 chunks of k=128 per group
    for (int T = 0; T < NT; T++) {
        if ((T & 3) == 0) {
#pragma unroll
            for (int mt = 0; mt < 2; mt++)
#pragma unroll
                for (int nt = 0; nt < 4; nt++)
#pragma unroll
                    for (int j = 0; j < 4; j++) acc[mt][nt][j] = 0;
        }
        if (T + 1 < NT) { stage_B(sb, T + 1); CP_COMMIT(); }

        unsigned bbase = sb + SMEM_A_BYTES + (unsigned)(T & 1) * SMEM_B_BYTES;
        int kchunk = (T & 3) * 128;          // byte offset within A row
#pragma unroll
        for (int ks = 0; ks < 4; ks++) {     // 4 x k32 per chunk
            unsigned aa[2][4];
#pragma unroll
            for (int mt = 0; mt < 2; mt++) {
                // x4: (rows 0-7,kb)(rows 8-15,kb)(rows 0-7,kb+16)(rows 8-15,kb+16)
                int row = wr * 32 + mt * 16 + ((lane >> 3) & 1) * 8 + (lane & 7);
                int kb  = kchunk + ks * 32 + ((lane >> 4) << 4);
                LDSM_X4(aa[mt], sb + a_off(row, kb));
            }
            unsigned bb[2][4];
#pragma unroll
            for (int p = 0; p < 2; p++) {
                // x4: (cols 0-7,kb)(cols 0-7,kb+16)(cols 8-15,kb)(cols 8-15,kb+16)
                int col = wc * 32 + p * 16 + ((lane >> 4) & 1) * 8 + (lane & 7);
                int kb  = ks * 32 + (((lane >> 3) & 1) << 4);
                LDSM_X4(bb[p], bbase + b_off(col, kb));
            }
#pragma unroll
            for (int mt = 0; mt < 2; mt++)
#pragma unroll
                for (int nt = 0; nt < 4; nt++)
                    MMA_S8(acc[mt][nt], aa[mt],
                           bb[nt >> 1][(nt & 1) * 2],
                           bb[nt >> 1][(nt & 1) * 2 + 1]);
        }

        if ((T & 3) == 3) {                  // epilogue for col group nc
            int nc = T >> 2;
#pragma unroll
            for (int nt = 0; nt < 4; nt++)
#pragma unroll
                for (int c = 0; c < 2; c++) {
                    int col = nc * 128 + wc * 32 + nt * 8 + (lane & 3) * 2 + c;
                    float c2v = g_c2[col];
                    float scv = g_sc[col];
#pragma unroll
                    for (int mt = 0; mt < 2; mt++)
#pragma unroll
                        for (int h = 0; h < 2; h++) {
                            float dotf = (float)acc[mt][nt][h * 2 + c];
                            float s = fmaf(-2.0f * sxr[mt * 2 + h] * scv,
                                           dotf, c2v);
                            ins8(t8[mt * 2 + h], packkey(s, col));
                        }
                }
        }
        CP_WAIT0();
        __syncthreads();
    }

    // merge top-8 across the 4 lanes of each quad (same rows, disjoint cols).
    // FETCH-THEN-INSERT: all partner keys read BEFORE any mutation (the R14
    // interleaved version read mid-mutation state -> duplicates -> flag storm).
#pragma unroll
    for (int r = 0; r < 4; r++) {
#pragma unroll
        for (int x = 1; x <= 2; x <<= 1) {
            unsigned o[8];
#pragma unroll
            for (int j = 0; j < 8; j++)
                o[j] = __shfl_xor_sync(0xFFFFFFFFu, t8[r][j], x);
#pragma unroll
            for (int j = 0; j < 8; j++)
                ins8(t8[r], o[j]);
        }
    }

    // cross-warp merge: per-warp keys -> smem [row][wc][8] (reuses B region)
    unsigned* keys = (unsigned*)(smem + SMEM_A_BYTES);   // 128*32*4B = 16KB
#pragma unroll
    for (int r = 0; r < 4; r++) {
        int mt = r >> 1, h = r & 1;
        if ((lane & 3) == mt) {
            int rl = wr * 32 + mt * 16 + (lane >> 2) + h * 8;
            *(uint4*)&keys[rl * 32 + wc * 8]     =
                make_uint4(t8[r][0], t8[r][1], t8[r][2], t8[r][3]);
            *(uint4*)&keys[rl * 32 + wc * 8 + 4] =
                make_uint4(t8[r][4], t8[r][5], t8[r][6], t8[r][7]);
        }
    }
    __syncthreads();

    if (tid < 128) {
        unsigned g8[8];
#pragma unroll
        for (int j = 0; j < 8; j++) g8[j] = 0xFFFFFFFFu;
#pragma unroll
        for (int w = 0; w < 4; w++) {
            uint4 v0 = *(uint4*)&keys[tid * 32 + w * 8];
            uint4 v1 = *(uint4*)&keys[tid * 32 + w * 8 + 4];
            ins8(g8, v0.x); ins8(g8, v0.y); ins8(g8, v0.z); ins8(g8, v0.w);
            ins8(g8, v1.x); ins8(g8, v1.y); ins8(g8, v1.z); ins8(g8, v1.w);
        }
        int row = blockRow + tid;
        out[row] = (float)(g8[0] & 2047u);
        float v1 = unpackv(g8[0]);
        float v2 = unpackv(g8[1]);
        if (v2 - v1 < FLAG_THRESH) {
            int ix = atomicAdd(&g_flag_count, 1);
            if (ix < FLAG_CAP) {
                g_flag_rows[ix] = row;
                g_flag_cand_lo[ix] = make_int4(
                    (int)(g8[0] & 2047u), (int)(g8[1] & 2047u),
                    (int)(g8[2] & 2047u), (int)(g8[3] & 2047u));
                g_flag_cand_hi[ix] = make_int4(
                    (int)(g8[4] & 2047u), (int)(g8[5] & 2047u),
                    (int)(g8[6] & 2047u), (int)(g8[7] & 2047u));
            }
        }
    }
}

// --- exact fp32 refinement of flagged rows (warp per row, 8 candidates) ----
__global__ void refine_kernel(const float* __restrict__ X,
                              const float* __restrict__ Cm,
                              float* __restrict__ out) {
    int nf = g_flag_count; if (nf > FLAG_CAP) nf = FLAG_CAP;
    int gw = (int)((blockIdx.x * blockDim.x + threadIdx.x) >> 5);
    int lane = threadIdx.x & 31;
    int nwarps = (int)((gridDim.x * blockDim.x) >> 5);
    for (int i = gw; i < nf; i += nwarps) {
        int row = g_flag_rows[i];
        int4 lo = g_flag_cand_lo[i];
        int4 hi = g_flag_cand_hi[i];
        int cand[8] = {lo.x, lo.y, lo.z, lo.w, hi.x, hi.y, hi.z, hi.w};
        const float* x = X + (long long)row * C_DIM;
        float bv = 3.4e38f; int bi = 0x7FFFFFFF;
#pragma unroll
        for (int c = 0; c < 8; c++) {
            int col = cand[c];
            const float* ce = Cm + (long long)col * C_DIM;
            float p = 0.0f;
#pragma unroll
            for (int d = 0; d < C_DIM / 32; d++)
                p = fmaf(x[lane + d * 32], ce[lane + d * 32], p);
#pragma unroll
            for (int o = 16; o > 0; o >>= 1)
                p += __shfl_xor_sync(0xFFFFFFFFu, p, o);
            float s = fmaf(-2.0f, p, g_c2[col]);
            if (s < bv || (s == bv && col < bi)) { bv = s; bi = col; }
        }
        if (lane == 0) out[row] = (float)bi;
    }
}

// ============================================================================
extern "C" void kernel_launch(void* const* d_in, const int* in_sizes, int n_in,
                              void* d_out, int out_size) {
    int n0 = in_sizes[0] / C_DIM;
    int n1 = in_sizes[1] / C_DIM;
    const float* X; const float* Cm; int N, K;
    if (n0 >= n1) { X = (const float*)d_in[0]; N = n0;
                    Cm = (const float*)d_in[1]; K = n1; }
    else          { X = (const float*)d_in[1]; N = n1;
                    Cm = (const float*)d_in[0]; K = n0; }
    if (N > N_CAP) N = N_CAP;
    if (K > K_CAP) K = K_CAP;
    float* out = (float*)d_out;

    cudaFuncSetAttribute(assign_mma,
                         cudaFuncAttributeMaxDynamicSharedMemorySize,
                         SMEM_TOTAL);

    // 1) quantize X to int8 (per-row scale) + flag counter reset
    convx8_kernel<<<(N + 7) / 8, 256>>>(X, N);
    // 2) centroid exact norms + int8 quantization
    c2s_kernel<<<(K * 32 + 255) / 256, 256>>>(Cm, K);
    // 3) int8 tensor-core GEMM + fused top-8 argmin
    assign_mma<<<N / 128, NTHREADS, SMEM_TOTAL>>>(out, K);
    // 4) exact fp32 refinement of near-tie rows (wide grid: latency-bound)
    refine_kernel<<<2048, 256>>>(X, Cm, out);
}

// round 16
// speedup vs baseline: 1.1627x; 1.1627x over previous
#include <cuda_runtime.h>

// ============================================================================
// KmeansAssigner: out[n] = argmin_k ( ||c_k||^2 - 2 * x_n . c_k )
// N=131072 C=512 K=2048.
//
// Round 16: R15 (881us, rel_err 0) carried 32 regs of top-8 state through the
// hot loop (spill/pressure: assign +130us vs R13). Depth-8 is only needed in
// the FINAL merges: per-thread top-4 (ins4, 16 regs, R13-fast epilogue) ->
// end-game quad/cross-warp merges at depth 8 -> 8-candidate exact fp32
// refine. True-argmin miss probability ~1e-7 per chip.
// ============================================================================

#define C_DIM 512
#define N_CAP 131072
#define K_CAP 2048
#define FLAG_CAP 131072
#define FLAG_THRESH 6.0f

#define SMEM_A_BYTES 65536             // 128 rows x 512B (int8)
#define SMEM_B_BYTES 16384             // 128 cols x 128B (int8 k-chunk)
#define SMEM_SX_OFF  (SMEM_A_BYTES + 2 * SMEM_B_BYTES)
#define SMEM_TOTAL   (SMEM_SX_OFF + 512)
#define NTHREADS 512

__device__ signed char g_X8[(size_t)N_CAP * C_DIM];
__device__ signed char g_C8[(size_t)K_CAP * C_DIM];
__device__ float g_sx[N_CAP];
__device__ float g_sc[K_CAP];
__device__ float g_c2[K_CAP];
__device__ int   g_flag_count;
__device__ int   g_flag_rows[FLAG_CAP];
__device__ int4  g_flag_cand_lo[FLAG_CAP];
__device__ int4  g_flag_cand_hi[FLAG_CAP];

// ---------------------------------------------------------------------------
__device__ __forceinline__ unsigned smem_u32(const void* p) {
    unsigned a;
    asm("{ .reg .u64 t; cvta.to.shared.u64 t, %1; cvt.u32.u64 %0, t; }"
        : "=r"(a) : "l"(p));
    return a;
}
#define CP16(dst, src)                                                         \
    asm volatile("cp.async.cg.shared.global [%0], [%1], 16;"                   \
                 :: "r"(dst), "l"(src) : "memory")
#define CP_COMMIT() asm volatile("cp.async.commit_group;" ::: "memory")
#define CP_WAIT0()  asm volatile("cp.async.wait_group 0;" ::: "memory")
#define LDSM_X4(R, addr)                                                       \
    asm volatile("ldmatrix.sync.aligned.m8n8.x4.shared.b16 {%0,%1,%2,%3}, [%4];" \
                 : "=r"((R)[0]), "=r"((R)[1]), "=r"((R)[2]), "=r"((R)[3])      \
                 : "r"(addr))
#define MMA_S8(Cc, A, B0, B1)                                                  \
    asm volatile("mma.sync.aligned.m16n8k32.row.col.s32.s8.s8.s32 "            \
                 "{%0,%1,%2,%3}, {%4,%5,%6,%7}, {%8,%9}, {%0,%1,%2,%3};"       \
                 : "+r"((Cc)[0]), "+r"((Cc)[1]), "+r"((Cc)[2]), "+r"((Cc)[3])  \
                 : "r"((A)[0]), "r"((A)[1]), "r"((A)[2]), "r"((A)[3]),         \
                   "r"(B0), "r"(B1))

// A smem: [128 rows][512B], XOR swizzle inside 128B blocks (kb mult of 16).
__device__ __forceinline__ unsigned a_off(int row, int kb) {
    return (unsigned)(row * 512 + (kb & ~127) +
                      ((((kb >> 4) & 7) ^ (row & 7)) << 4));
}
// B smem: [128 cols][128B] (one 128-elem int8 k-chunk per col), XOR swizzle.
__device__ __forceinline__ unsigned b_off(int col, int kb) {
    return (unsigned)(col * 128 + ((((kb >> 4) & 7) ^ (col & 7)) << 4));
}

// order-preserving float->uint, low 11 bits replaced by col (tiebreak low col)
__device__ __forceinline__ unsigned packkey(float s, int col) {
    unsigned u = __float_as_uint(s);
    u ^= (unsigned)(((int)u >> 31)) | 0x80000000u;
    return (u & ~2047u) | (unsigned)col;
}
__device__ __forceinline__ float unpackv(unsigned key) {
    unsigned u = (key & 0x80000000u) ? (key ^ 0x80000000u) : ~key;
    return __uint_as_float(u);
}
// sorted insert into ascending t[0..3]  (hot-loop path, cheap)
__device__ __forceinline__ void ins4(unsigned* t, unsigned k) {
    if (k < t[3]) {
        if (k < t[1]) {
            t[3] = t[2]; t[2] = t[1];
            if (k < t[0]) { t[1] = t[0]; t[0] = k; } else t[1] = k;
        } else {
            if (k < t[2]) { t[3] = t[2]; t[2] = k; } else t[3] = k;
        }
    }
}
// sorted insert into ascending t[0..7]  (end-game merges only)
__device__ __forceinline__ void ins8(unsigned* t, unsigned k) {
    if (k < t[7]) {
        t[7] = k;
#pragma unroll
        for (int j = 7; j > 0; j--) {
            unsigned a = t[j - 1], b = t[j];
            t[j - 1] = a < b ? a : b;
            t[j]     = a < b ? b : a;
        }
    }
}
__device__ __forceinline__ int q8(float v, float inv) {
    int q = __float2int_rn(v * inv);
    return q < -127 ? -127 : (q > 127 ? 127 : q);
}
__device__ __forceinline__ unsigned pack4(const float* v, float inv) {
    return (unsigned)(q8(v[0], inv) & 255) |
           ((unsigned)(q8(v[1], inv) & 255) << 8) |
           ((unsigned)(q8(v[2], inv) & 255) << 16) |
           ((unsigned)(q8(v[3], inv) & 255) << 24);
}

// --- quantize X rows to int8 (per-row scale); reset flag counter -----------
__global__ void convx8_kernel(const float* __restrict__ X, int N) {
    if (blockIdx.x == 0 && threadIdx.x == 0) g_flag_count = 0;
    int row = (int)blockIdx.x * 8 + (threadIdx.x >> 5);
    int lane = threadIdx.x & 31;
    if (row >= N) return;
    const float4* src = (const float4*)(X + (size_t)row * C_DIM) + lane * 4;
    float4 v[4];
    float mx = 0.0f;
#pragma unroll
    for (int i = 0; i < 4; i++) {
        v[i] = src[i];
        mx = fmaxf(mx, fmaxf(fmaxf(fabsf(v[i].x), fabsf(v[i].y)),
                             fmaxf(fabsf(v[i].z), fabsf(v[i].w))));
    }
#pragma unroll
    for (int o = 16; o > 0; o >>= 1)
        mx = fmaxf(mx, __shfl_xor_sync(0xFFFFFFFFu, mx, o));
    mx = fmaxf(mx, 1e-20f);
    float inv = 127.0f / mx;
    int4 p;
    p.x = (int)pack4(&v[0].x, inv);
    p.y = (int)pack4(&v[1].x, inv);
    p.z = (int)pack4(&v[2].x, inv);
    p.w = (int)pack4(&v[3].x, inv);
    ((int4*)(g_X8 + (size_t)row * C_DIM))[lane] = p;
    if (lane == 0) g_sx[row] = mx / 127.0f;
}

// --- centroid: exact ||c||^2 (fp32) + int8 quantization, warp per row ------
__global__ void c2s_kernel(const float* __restrict__ cent, int K) {
    int row = (int)((blockIdx.x * blockDim.x + threadIdx.x) >> 5);
    int lane = threadIdx.x & 31;
    if (row >= K || row >= K_CAP) return;
    const float4* src = (const float4*)(cent + (size_t)row * C_DIM) + lane * 4;
    float4 v[4];
    float mx = 0.0f, s2 = 0.0f;
#pragma unroll
    for (int i = 0; i < 4; i++) {
        v[i] = src[i];
        mx = fmaxf(mx, fmaxf(fmaxf(fabsf(v[i].x), fabsf(v[i].y)),
                             fmaxf(fabsf(v[i].z), fabsf(v[i].w))));
        s2 = fmaf(v[i].x, v[i].x, s2); s2 = fmaf(v[i].y, v[i].y, s2);
        s2 = fmaf(v[i].z, v[i].z, s2); s2 = fmaf(v[i].w, v[i].w, s2);
    }
#pragma unroll
    for (int o = 16; o > 0; o >>= 1) {
        mx = fmaxf(mx, __shfl_xor_sync(0xFFFFFFFFu, mx, o));
        s2 += __shfl_xor_sync(0xFFFFFFFFu, s2, o);
    }
    mx = fmaxf(mx, 1e-20f);
    float inv = 127.0f / mx;
    int4 p;
    p.x = (int)pack4(&v[0].x, inv);
    p.y = (int)pack4(&v[1].x, inv);
    p.z = (int)pack4(&v[2].x, inv);
    p.w = (int)pack4(&v[3].x, inv);
    ((int4*)(g_C8 + (size_t)row * C_DIM))[lane] = p;
    if (lane == 0) { g_sc[row] = mx / 127.0f; g_c2[row] = s2; }
}

// --- B chunk staging (16KB: 128 cols x 128 int8 k) -------------------------
__device__ __forceinline__ void stage_B(unsigned sb, int T) {
    int nc = T >> 2, kk = T & 3, buf = T & 1;
    int tid = threadIdx.x;
    const signed char* srcb = g_C8 + ((size_t)nc * 128) * C_DIM + kk * 128;
    unsigned base = sb + SMEM_A_BYTES + (unsigned)buf * SMEM_B_BYTES;
#pragma unroll
    for (int i = 0; i < 2; i++) {
        int idx = tid + i * NTHREADS;         // 16B granule 0..1023
        int col = idx >> 3, u = idx & 7;
        unsigned dst = base + (unsigned)(col * 128 + ((u ^ (col & 7)) << 4));
        const void* s = srcb + (size_t)col * C_DIM + u * 16;
        CP16(dst, s);
    }
}

// --- main: int8 mma.sync GEMM + fused argmin (top-4 hot / top-8 merge) -----
__global__ void __launch_bounds__(NTHREADS, 1)
assign_mma(float* __restrict__ out, int K) {
    extern __shared__ char smem[];
    unsigned sb = smem_u32(smem);
    const int tid = threadIdx.x, lane = tid & 31, wid = tid >> 5;
    const int wr = wid >> 2, wc = wid & 3;   // warp grid 4 (rows) x 4 (cols)
    const int blockRow = (int)blockIdx.x * 128;
    float* sxs = (float*)(smem + SMEM_SX_OFF);

    // prologue: stage A tile (128 rows x 512 int8 = 64KB) + sx + B chunk 0
    {
        const signed char* src = g_X8 + (size_t)blockRow * C_DIM;
#pragma unroll
        for (int i = 0; i < 8; i++) {
            int idx = tid + i * NTHREADS;     // 16B granule 0..4095
            int row = idx >> 5, u = idx & 31;
            unsigned dst = sb + a_off(row, u * 16);
            const void* s = src + (size_t)row * C_DIM + u * 16;
            CP16(dst, s);
        }
    }
    if (tid < 128) sxs[tid] = g_sx[blockRow + tid];
    stage_B(sb, 0);
    CP_COMMIT();
    CP_WAIT0();
    __syncthreads();

    // per-thread row scales (rows: wr*32 + mt*16 + h*8 + lane/4)
    float sxr[4];
#pragma unroll
    for (int r = 0; r < 4; r++)
        sxr[r] = sxs[wr * 32 + (r >> 1) * 16 + (r & 1) * 8 + (lane >> 2)];

    int      acc[2][4][4];                   // warp tile 32 rows x 32 cols
    unsigned t4[4][4];                       // hot-loop state: top-4 per row
#pragma unroll
    for (int r = 0; r < 4; r++)
#pragma unroll
        for (int j = 0; j < 4; j++) t4[r][j] = 0xFFFFFFFFu;

    const int NT = (K / 128) * 4;            // 4 chunks of k=128 per group
    for (int T = 0; T < NT; T++) {
        if ((T & 3) == 0) {
#pragma unroll
            for (int mt = 0; mt < 2; mt++)
#pragma unroll
                for (int nt = 0; nt < 4; nt++)
#pragma unroll
                    for (int j = 0; j < 4; j++) acc[mt][nt][j] = 0;
        }
        if (T + 1 < NT) { stage_B(sb, T + 1); CP_COMMIT(); }

        unsigned bbase = sb + SMEM_A_BYTES + (unsigned)(T & 1) * SMEM_B_BYTES;
        int kchunk = (T & 3) * 128;          // byte offset within A row
#pragma unroll
        for (int ks = 0; ks < 4; ks++) {     // 4 x k32 per chunk
            unsigned aa[2][4];
#pragma unroll
            for (int mt = 0; mt < 2; mt++) {
                // x4: (rows 0-7,kb)(rows 8-15,kb)(rows 0-7,kb+16)(rows 8-15,kb+16)
                int row = wr * 32 + mt * 16 + ((lane >> 3) & 1) * 8 + (lane & 7);
                int kb  = kchunk + ks * 32 + ((lane >> 4) << 4);
                LDSM_X4(aa[mt], sb + a_off(row, kb));
            }
            unsigned bb[2][4];
#pragma unroll
            for (int p = 0; p < 2; p++) {
                // x4: (cols 0-7,kb)(cols 0-7,kb+16)(cols 8-15,kb)(cols 8-15,kb+16)
                int col = wc * 32 + p * 16 + ((lane >> 4) & 1) * 8 + (lane & 7);
                int kb  = ks * 32 + (((lane >> 3) & 1) << 4);
                LDSM_X4(bb[p], bbase + b_off(col, kb));
            }
#pragma unroll
            for (int mt = 0; mt < 2; mt++)
#pragma unroll
                for (int nt = 0; nt < 4; nt++)
                    MMA_S8(acc[mt][nt], aa[mt],
                           bb[nt >> 1][(nt & 1) * 2],
                           bb[nt >> 1][(nt & 1) * 2 + 1]);
        }

        if ((T & 3) == 3) {                  // epilogue for col group nc
            int nc = T >> 2;
#pragma unroll
            for (int nt = 0; nt < 4; nt++)
#pragma unroll
                for (int c = 0; c < 2; c++) {
                    int col = nc * 128 + wc * 32 + nt * 8 + (lane & 3) * 2 + c;
                    float c2v = g_c2[col];
                    float scv = g_sc[col];
#pragma unroll
                    for (int mt = 0; mt < 2; mt++)
#pragma unroll
                        for (int h = 0; h < 2; h++) {
                            float dotf = (float)acc[mt][nt][h * 2 + c];
                            float s = fmaf(-2.0f * sxr[mt * 2 + h] * scv,
                                           dotf, c2v);
                            ins4(t4[mt * 2 + h], packkey(s, col));
                        }
                }
        }
        CP_WAIT0();
        __syncthreads();
    }

    // === END-GAME MERGES (depth 8, off the hot loop) ========================
    // Quad merge: 4 lanes hold per-subset top-4s for the same rows.
    // Expand to depth-8 and fetch-then-insert (all reads before any mutation).
    unsigned* keys = (unsigned*)(smem + SMEM_A_BYTES);   // 128*32*4B = 16KB
#pragma unroll
    for (int r = 0; r < 4; r++) {
        unsigned m8[8];
#pragma unroll
        for (int j = 0; j < 4; j++) m8[j] = t4[r][j];
#pragma unroll
        for (int j = 4; j < 8; j++) m8[j] = 0xFFFFFFFFu;
#pragma unroll
        for (int x = 1; x <= 2; x <<= 1) {
            unsigned o[8];
#pragma unroll
            for (int j = 0; j < 8; j++)
                o[j] = __shfl_xor_sync(0xFFFFFFFFu, m8[j], x);
#pragma unroll
            for (int j = 0; j < 8; j++)
                ins8(m8, o[j]);
        }
        int mt = r >> 1, h = r & 1;
        if ((lane & 3) == mt) {
            int rl = wr * 32 + mt * 16 + (lane >> 2) + h * 8;
            *(uint4*)&keys[rl * 32 + wc * 8]     =
                make_uint4(m8[0], m8[1], m8[2], m8[3]);
            *(uint4*)&keys[rl * 32 + wc * 8 + 4] =
                make_uint4(m8[4], m8[5], m8[6], m8[7]);
        }
    }
    __syncthreads();

    // Cross-warp merge: one thread per row merges 4 warps x 8 keys -> top-8.
    if (tid < 128) {
        unsigned g8[8];
#pragma unroll
        for (int j = 0; j < 8; j++) g8[j] = 0xFFFFFFFFu;
#pragma unroll
        for (int w = 0; w < 4; w++) {
            uint4 v0 = *(uint4*)&keys[tid * 32 + w * 8];
            uint4 v1 = *(uint4*)&keys[tid * 32 + w * 8 + 4];
            ins8(g8, v0.x); ins8(g8, v0.y); ins8(g8, v0.z); ins8(g8, v0.w);
            ins8(g8, v1.x); ins8(g8, v1.y); ins8(g8, v1.z); ins8(g8, v1.w);
        }
        int row = blockRow + tid;
        out[row] = (float)(g8[0] & 2047u);
        float v1 = unpackv(g8[0]);
        float v2 = unpackv(g8[1]);
        if (v2 - v1 < FLAG_THRESH) {
            int ix = atomicAdd(&g_flag_count, 1);
            if (ix < FLAG_CAP) {
                g_flag_rows[ix] = row;
                g_flag_cand_lo[ix] = make_int4(
                    (int)(g8[0] & 2047u), (int)(g8[1] & 2047u),
                    (int)(g8[2] & 2047u), (int)(g8[3] & 2047u));
                g_flag_cand_hi[ix] = make_int4(
                    (int)(g8[4] & 2047u), (int)(g8[5] & 2047u),
                    (int)(g8[6] & 2047u), (int)(g8[7] & 2047u));
            }
        }
    }
}

// --- exact fp32 refinement of flagged rows (warp per row, 8 candidates) ----
__global__ void refine_kernel(const float* __restrict__ X,
                              const float* __restrict__ Cm,
                              float* __restrict__ out) {
    int nf = g_flag_count; if (nf > FLAG_CAP) nf = FLAG_CAP;
    int gw = (int)((blockIdx.x * blockDim.x + threadIdx.x) >> 5);
    int lane = threadIdx.x & 31;
    int nwarps = (int)((gridDim.x * blockDim.x) >> 5);
    for (int i = gw; i < nf; i += nwarps) {
        int row = g_flag_rows[i];
        int4 lo = g_flag_cand_lo[i];
        int4 hi = g_flag_cand_hi[i];
        int cand[8] = {lo.x, lo.y, lo.z, lo.w, hi.x, hi.y, hi.z, hi.w};
        const float* x = X + (long long)row * C_DIM;
        float bv = 3.4e38f; int bi = 0x7FFFFFFF;
#pragma unroll
        for (int c = 0; c < 8; c++) {
            int col = cand[c];
            const float* ce = Cm + (long long)col * C_DIM;
            float p = 0.0f;
#pragma unroll
            for (int d = 0; d < C_DIM / 32; d++)
                p = fmaf(x[lane + d * 32], ce[lane + d * 32], p);
#pragma unroll
            for (int o = 16; o > 0; o >>= 1)
                p += __shfl_xor_sync(0xFFFFFFFFu, p, o);
            float s = fmaf(-2.0f, p, g_c2[col]);
            if (s < bv || (s == bv && col < bi)) { bv = s; bi = col; }
        }
        if (lane == 0) out[row] = (float)bi;
    }
}

// ============================================================================
extern "C" void kernel_launch(void* const* d_in, const int* in_sizes, int n_in,
                              void* d_out, int out_size) {
    int n0 = in_sizes[0] / C_DIM;
    int n1 = in_sizes[1] / C_DIM;
    const float* X; const float* Cm; int N, K;
    if (n0 >= n1) { X = (const float*)d_in[0]; N = n0;
                    Cm = (const float*)d_in[1]; K = n1; }
    else          { X = (const float*)d_in[1]; N = n1;
                    Cm = (const float*)d_in[0]; K = n0; }
    if (N > N_CAP) N = N_CAP;
    if (K > K_CAP) K = K_CAP;
    float* out = (float*)d_out;

    cudaFuncSetAttribute(assign_mma,
                         cudaFuncAttributeMaxDynamicSharedMemorySize,
                         SMEM_TOTAL);

    // 1) quantize X to int8 (per-row scale) + flag counter reset
    convx8_kernel<<<(N + 7) / 8, 256>>>(X, N);
    // 2) centroid exact norms + int8 quantization
    c2s_kernel<<<(K * 32 + 255) / 256, 256>>>(Cm, K);
    // 3) int8 tensor-core GEMM + fused argmin (top-4 hot loop, top-8 merge)
    assign_mma<<<N / 128, NTHREADS, SMEM_TOTAL>>>(out, K);
    // 4) exact fp32 refinement of near-tie rows (wide grid: latency-bound)
    refine_kernel<<<2048, 256>>>(X, Cm, out);
}

// round 17
// speedup vs baseline: 1.1649x; 1.0019x over previous
#include <cuda_runtime.h>

// ============================================================================
// KmeansAssigner: out[n] = argmin_k ( ||c_k||^2 - 2 * x_n . c_k )
// N=131072 C=512 K=2048.
//
// Round 16: R15 (881us, rel_err 0) carried 32 regs of top-8 state through the
// hot loop (spill/pressure: assign +130us vs R13). Depth-8 is only needed in
// the FINAL merges: per-thread top-4 (ins4, 16 regs, R13-fast epilogue) ->
// end-game quad/cross-warp merges at depth 8 -> 8-candidate exact fp32
// refine. True-argmin miss probability ~1e-7 per chip.
// ============================================================================

#define C_DIM 512
#define N_CAP 131072
#define K_CAP 2048
#define FLAG_CAP 131072
#define FLAG_THRESH 6.0f

#define SMEM_A_BYTES 65536             // 128 rows x 512B (int8)
#define SMEM_B_BYTES 16384             // 128 cols x 128B (int8 k-chunk)
#define SMEM_SX_OFF  (SMEM_A_BYTES + 2 * SMEM_B_BYTES)
#define SMEM_TOTAL   (SMEM_SX_OFF + 512)
#define NTHREADS 512

__device__ signed char g_X8[(size_t)N_CAP * C_DIM];
__device__ signed char g_C8[(size_t)K_CAP * C_DIM];
__device__ float g_sx[N_CAP];
__device__ float g_sc[K_CAP];
__device__ float g_c2[K_CAP];
__device__ int   g_flag_count;
__device__ int   g_flag_rows[FLAG_CAP];
__device__ int4  g_flag_cand_lo[FLAG_CAP];
__device__ int4  g_flag_cand_hi[FLAG_CAP];

// ---------------------------------------------------------------------------
__device__ __forceinline__ unsigned smem_u32(const void* p) {
    unsigned a;
    asm("{ .reg .u64 t; cvta.to.shared.u64 t, %1; cvt.u32.u64 %0, t; }"
        : "=r"(a) : "l"(p));
    return a;
}
#define CP16(dst, src)                                                         \
    asm volatile("cp.async.cg.shared.global [%0], [%1], 16;"                   \
                 :: "r"(dst), "l"(src) : "memory")
#define CP_COMMIT() asm volatile("cp.async.commit_group;" ::: "memory")
#define CP_WAIT0()  asm volatile("cp.async.wait_group 0;" ::: "memory")
#define LDSM_X4(R, addr)                                                       \
    asm volatile("ldmatrix.sync.aligned.m8n8.x4.shared.b16 {%0,%1,%2,%3}, [%4];" \
                 : "=r"((R)[0]), "=r"((R)[1]), "=r"((R)[2]), "=r"((R)[3])      \
                 : "r"(addr))
#define MMA_S8(Cc, A, B0, B1)                                                  \
    asm volatile("mma.sync.aligned.m16n8k32.row.col.s32.s8.s8.s32 "            \
                 "{%0,%1,%2,%3}, {%4,%5,%6,%7}, {%8,%9}, {%0,%1,%2,%3};"       \
                 : "+r"((Cc)[0]), "+r"((Cc)[1]), "+r"((Cc)[2]), "+r"((Cc)[3])  \
                 : "r"((A)[0]), "r"((A)[1]), "r"((A)[2]), "r"((A)[3]),         \
                   "r"(B0), "r"(B1))

// A smem: [128 rows][512B], XOR swizzle inside 128B blocks (kb mult of 16).
__device__ __forceinline__ unsigned a_off(int row, int kb) {
    return (unsigned)(row * 512 + (kb & ~127) +
                      ((((kb >> 4) & 7) ^ (row & 7)) << 4));
}
// B smem: [128 cols][128B] (one 128-elem int8 k-chunk per col), XOR swizzle.
__device__ __forceinline__ unsigned b_off(int col, int kb) {
    return (unsigned)(col * 128 + ((((kb >> 4) & 7) ^ (col & 7)) << 4));
}

// order-preserving float->uint, low 11 bits replaced by col (tiebreak low col)
__device__ __forceinline__ unsigned packkey(float s, int col) {
    unsigned u = __float_as_uint(s);
    u ^= (unsigned)(((int)u >> 31)) | 0x80000000u;
    return (u & ~2047u) | (unsigned)col;
}
__device__ __forceinline__ float unpackv(unsigned key) {
    unsigned u = (key & 0x80000000u) ? (key ^ 0x80000000u) : ~key;
    return __uint_as_float(u);
}
// sorted insert into ascending t[0..3]  (hot-loop path, cheap)
__device__ __forceinline__ void ins4(unsigned* t, unsigned k) {
    if (k < t[3]) {
        if (k < t[1]) {
            t[3] = t[2]; t[2] = t[1];
            if (k < t[0]) { t[1] = t[0]; t[0] = k; } else t[1] = k;
        } else {
            if (k < t[2]) { t[3] = t[2]; t[2] = k; } else t[3] = k;
        }
    }
}
// sorted insert into ascending t[0..7]  (end-game merges only)
__device__ __forceinline__ void ins8(unsigned* t, unsigned k) {
    if (k < t[7]) {
        t[7] = k;
#pragma unroll
        for (int j = 7; j > 0; j--) {
            unsigned a = t[j - 1], b = t[j];
            t[j - 1] = a < b ? a : b;
            t[j]     = a < b ? b : a;
        }
    }
}
__device__ __forceinline__ int q8(float v, float inv) {
    int q = __float2int_rn(v * inv);
    return q < -127 ? -127 : (q > 127 ? 127 : q);
}
__device__ __forceinline__ unsigned pack4(const float* v, float inv) {
    return (unsigned)(q8(v[0], inv) & 255) |
           ((unsigned)(q8(v[1], inv) & 255) << 8) |
           ((unsigned)(q8(v[2], inv) & 255) << 16) |
           ((unsigned)(q8(v[3], inv) & 255) << 24);
}

// --- quantize X rows to int8 (per-row scale); reset flag counter -----------
__global__ void convx8_kernel(const float* __restrict__ X, int N) {
    if (blockIdx.x == 0 && threadIdx.x == 0) g_flag_count = 0;
    int row = (int)blockIdx.x * 8 + (threadIdx.x >> 5);
    int lane = threadIdx.x & 31;
    if (row >= N) return;
    const float4* src = (const float4*)(X + (size_t)row * C_DIM) + lane * 4;
    float4 v[4];
    float mx = 0.0f;
#pragma unroll
    for (int i = 0; i < 4; i++) {
        v[i] = src[i];
        mx = fmaxf(mx, fmaxf(fmaxf(fabsf(v[i].x), fabsf(v[i].y)),
                             fmaxf(fabsf(v[i].z), fabsf(v[i].w))));
    }
#pragma unroll
    for (int o = 16; o > 0; o >>= 1)
        mx = fmaxf(mx, __shfl_xor_sync(0xFFFFFFFFu, mx, o));
    mx = fmaxf(mx, 1e-20f);
    float inv = 127.0f / mx;
    int4 p;
    p.x = (int)pack4(&v[0].x, inv);
    p.y = (int)pack4(&v[1].x, inv);
    p.z = (int)pack4(&v[2].x, inv);
    p.w = (int)pack4(&v[3].x, inv);
    ((int4*)(g_X8 + (size_t)row * C_DIM))[lane] = p;
    if (lane == 0) g_sx[row] = mx / 127.0f;
}

// --- centroid: exact ||c||^2 (fp32) + int8 quantization, warp per row ------
__global__ void c2s_kernel(const float* __restrict__ cent, int K) {
    int row = (int)((blockIdx.x * blockDim.x + threadIdx.x) >> 5);
    int lane = threadIdx.x & 31;
    if (row >= K || row >= K_CAP) return;
    const float4* src = (const float4*)(cent + (size_t)row * C_DIM) + lane * 4;
    float4 v[4];
    float mx = 0.0f, s2 = 0.0f;
#pragma unroll
    for (int i = 0; i < 4; i++) {
        v[i] = src[i];
        mx = fmaxf(mx, fmaxf(fmaxf(fabsf(v[i].x), fabsf(v[i].y)),
                             fmaxf(fabsf(v[i].z), fabsf(v[i].w))));
        s2 = fmaf(v[i].x, v[i].x, s2); s2 = fmaf(v[i].y, v[i].y, s2);
        s2 = fmaf(v[i].z, v[i].z, s2); s2 = fmaf(v[i].w, v[i].w, s2);
    }
#pragma unroll
    for (int o = 16; o > 0; o >>= 1) {
        mx = fmaxf(mx, __shfl_xor_sync(0xFFFFFFFFu, mx, o));
        s2 += __shfl_xor_sync(0xFFFFFFFFu, s2, o);
    }
    mx = fmaxf(mx, 1e-20f);
    float inv = 127.0f / mx;
    int4 p;
    p.x = (int)pack4(&v[0].x, inv);
    p.y = (int)pack4(&v[1].x, inv);
    p.z = (int)pack4(&v[2].x, inv);
    p.w = (int)pack4(&v[3].x, inv);
    ((int4*)(g_C8 + (size_t)row * C_DIM))[lane] = p;
    if (lane == 0) { g_sc[row] = mx / 127.0f; g_c2[row] = s2; }
}

// --- B chunk staging (16KB: 128 cols x 128 int8 k) -------------------------
__device__ __forceinline__ void stage_B(unsigned sb, int T) {
    int nc = T >> 2, kk = T & 3, buf = T & 1;
    int tid = threadIdx.x;
    const signed char* srcb = g_C8 + ((size_t)nc * 128) * C_DIM + kk * 128;
    unsigned base = sb + SMEM_A_BYTES + (unsigned)buf * SMEM_B_BYTES;
#pragma unroll
    for (int i = 0; i < 2; i++) {
        int idx = tid + i * NTHREADS;         // 16B granule 0..1023
        int col = idx >> 3, u = idx & 7;
        unsigned dst = base + (unsigned)(col * 128 + ((u ^ (col & 7)) << 4));
        const void* s = srcb + (size_t)col * C_DIM + u * 16;
        CP16(dst, s);
    }
}

// --- main: int8 mma.sync GEMM + fused argmin (top-4 hot / top-8 merge) -----
__global__ void __launch_bounds__(NTHREADS, 1)
assign_mma(float* __restrict__ out, int K) {
    extern __shared__ char smem[];
    unsigned sb = smem_u32(smem);
    const int tid = threadIdx.x, lane = tid & 31, wid = tid >> 5;
    const int wr = wid >> 2, wc = wid & 3;   // warp grid 4 (rows) x 4 (cols)
    const int blockRow = (int)blockIdx.x * 128;
    float* sxs = (float*)(smem + SMEM_SX_OFF);

    // prologue: stage A tile (128 rows x 512 int8 = 64KB) + sx + B chunk 0
    {
        const signed char* src = g_X8 + (size_t)blockRow * C_DIM;
#pragma unroll
        for (int i = 0; i < 8; i++) {
            int idx = tid + i * NTHREADS;     // 16B granule 0..4095
            int row = idx >> 5, u = idx & 31;
            unsigned dst = sb + a_off(row, u * 16);
            const void* s = src + (size_t)row * C_DIM + u * 16;
            CP16(dst, s);
        }
    }
    if (tid < 128) sxs[tid] = g_sx[blockRow + tid];
    stage_B(sb, 0);
    CP_COMMIT();
    CP_WAIT0();
    __syncthreads();

    // per-thread row scales (rows: wr*32 + mt*16 + h*8 + lane/4)
    float sxr[4];
#pragma unroll
    for (int r = 0; r < 4; r++)
        sxr[r] = sxs[wr * 32 + (r >> 1) * 16 + (r & 1) * 8 + (lane >> 2)];

    int      acc[2][4][4];                   // warp tile 32 rows x 32 cols
    unsigned t4[4][4];                       // hot-loop state: top-4 per row
#pragma unroll
    for (int r = 0; r < 4; r++)
#pragma unroll
        for (int j = 0; j < 4; j++) t4[r][j] = 0xFFFFFFFFu;

    const int NT = (K / 128) * 4;            // 4 chunks of k=128 per group
    for (int T = 0; T < NT; T++) {
        if ((T & 3) == 0) {
#pragma unroll
            for (int mt = 0; mt < 2; mt++)
#pragma unroll
                for (int nt = 0; nt < 4; nt++)
#pragma unroll
                    for (int j = 0; j < 4; j++) acc[mt][nt][j] = 0;
        }
        if (T + 1 < NT) { stage_B(sb, T + 1); CP_COMMIT(); }

        unsigned bbase = sb + SMEM_A_BYTES + (unsigned)(T & 1) * SMEM_B_BYTES;
        int kchunk = (T & 3) * 128;          // byte offset within A row
#pragma unroll
        for (int ks = 0; ks < 4; ks++) {     // 4 x k32 per chunk
            unsigned aa[2][4];
#pragma unroll
            for (int mt = 0; mt < 2; mt++) {
                // x4: (rows 0-7,kb)(rows 8-15,kb)(rows 0-7,kb+16)(rows 8-15,kb+16)
                int row = wr * 32 + mt * 16 + ((lane >> 3) & 1) * 8 + (lane & 7);
                int kb  = kchunk + ks * 32 + ((lane >> 4) << 4);
                LDSM_X4(aa[mt], sb + a_off(row, kb));
            }
            unsigned bb[2][4];
#pragma unroll
            for (int p = 0; p < 2; p++) {
                // x4: (cols 0-7,kb)(cols 0-7,kb+16)(cols 8-15,kb)(cols 8-15,kb+16)
                int col = wc * 32 + p * 16 + ((lane >> 4) & 1) * 8 + (lane & 7);
                int kb  = ks * 32 + (((lane >> 3) & 1) << 4);
                LDSM_X4(bb[p], bbase + b_off(col, kb));
            }
#pragma unroll
            for (int mt = 0; mt < 2; mt++)
#pragma unroll
                for (int nt = 0; nt < 4; nt++)
                    MMA_S8(acc[mt][nt], aa[mt],
                           bb[nt >> 1][(nt & 1) * 2],
                           bb[nt >> 1][(nt & 1) * 2 + 1]);
        }

        if ((T & 3) == 3) {                  // epilogue for col group nc
            int nc = T >> 2;
#pragma unroll
            for (int nt = 0; nt < 4; nt++)
#pragma unroll
                for (int c = 0; c < 2; c++) {
                    int col = nc * 128 + wc * 32 + nt * 8 + (lane & 3) * 2 + c;
                    float c2v = g_c2[col];
                    float scv = g_sc[col];
#pragma unroll
                    for (int mt = 0; mt < 2; mt++)
#pragma unroll
                        for (int h = 0; h < 2; h++) {
                            float dotf = (float)acc[mt][nt][h * 2 + c];
                            float s = fmaf(-2.0f * sxr[mt * 2 + h] * scv,
                                           dotf, c2v);
                            ins4(t4[mt * 2 + h], packkey(s, col));
                        }
                }
        }
        CP_WAIT0();
        __syncthreads();
    }

    // === END-GAME MERGES (depth 8, off the hot loop) ========================
    // Quad merge: 4 lanes hold per-subset top-4s for the same rows.
    // Expand to depth-8 and fetch-then-insert (all reads before any mutation).
    unsigned* keys = (unsigned*)(smem + SMEM_A_BYTES);   // 128*32*4B = 16KB
#pragma unroll
    for (int r = 0; r < 4; r++) {
        unsigned m8[8];
#pragma unroll
        for (int j = 0; j < 4; j++) m8[j] = t4[r][j];
#pragma unroll
        for (int j = 4; j < 8; j++) m8[j] = 0xFFFFFFFFu;
#pragma unroll
        for (int x = 1; x <= 2; x <<= 1) {
            unsigned o[8];
#pragma unroll
            for (int j = 0; j < 8; j++)
                o[j] = __shfl_xor_sync(0xFFFFFFFFu, m8[j], x);
#pragma unroll
            for (int j = 0; j < 8; j++)
                ins8(m8, o[j]);
        }
        int mt = r >> 1, h = r & 1;
        if ((lane & 3) == mt) {
            int rl = wr * 32 + mt * 16 + (lane >> 2) + h * 8;
            *(uint4*)&keys[rl * 32 + wc * 8]     =
                make_uint4(m8[0], m8[1], m8[2], m8[3]);
            *(uint4*)&keys[rl * 32 + wc * 8 + 4] =
                make_uint4(m8[4], m8[5], m8[6], m8[7]);
        }
    }
    __syncthreads();

    // Cross-warp merge: one thread per row merges 4 warps x 8 keys -> top-8.
    if (tid < 128) {
        unsigned g8[8];
#pragma unroll
        for (int j = 0; j < 8; j++) g8[j] = 0xFFFFFFFFu;
#pragma unroll
        for (int w = 0; w < 4; w++) {
            uint4 v0 = *(uint4*)&keys[tid * 32 + w * 8];
            uint4 v1 = *(uint4*)&keys[tid * 32 + w * 8 + 4];
            ins8(g8, v0.x); ins8(g8, v0.y); ins8(g8, v0.z); ins8(g8, v0.w);
            ins8(g8, v1.x); ins8(g8, v1.y); ins8(g8, v1.z); ins8(g8, v1.w);
        }
        int row = blockRow + tid;
        out[row] = (float)(g8[0] & 2047u);
        float v1 = unpackv(g8[0]);
        float v2 = unpackv(g8[1]);
        if (v2 - v1 < FLAG_THRESH) {
            int ix = atomicAdd(&g_flag_count, 1);
            if (ix < FLAG_CAP) {
                g_flag_rows[ix] = row;
                g_flag_cand_lo[ix] = make_int4(
                    (int)(g8[0] & 2047u), (int)(g8[1] & 2047u),
                    (int)(g8[2] & 2047u), (int)(g8[3] & 2047u));
                g_flag_cand_hi[ix] = make_int4(
                    (int)(g8[4] & 2047u), (int)(g8[5] & 2047u),
                    (int)(g8[6] & 2047u), (int)(g8[7] & 2047u));
            }
        }
    }
}

// --- exact fp32 refinement of flagged rows (warp per row, 8 candidates) ----
__global__ void refine_kernel(const float* __restrict__ X,
                              const float* __restrict__ Cm,
                              float* __restrict__ out) {
    int nf = g_flag_count; if (nf > FLAG_CAP) nf = FLAG_CAP;
    int gw = (int)((blockIdx.x * blockDim.x + threadIdx.x) >> 5);
    int lane = threadIdx.x & 31;
    int nwarps = (int)((gridDim.x * blockDim.x) >> 5);
    for (int i = gw; i < nf; i += nwarps) {
        int row = g_flag_rows[i];
        int4 lo = g_flag_cand_lo[i];
        int4 hi = g_flag_cand_hi[i];
        int cand[8] = {lo.x, lo.y, lo.z, lo.w, hi.x, hi.y, hi.z, hi.w};
        const float* x = X + (long long)row * C_DIM;
        float bv = 3.4e38f; int bi = 0x7FFFFFFF;
#pragma unroll
        for (int c = 0; c < 8; c++) {
            int col = cand[c];
            const float* ce = Cm + (long long)col * C_DIM;
            float p = 0.0f;
#pragma unroll
            for (int d = 0; d < C_DIM / 32; d++)
                p = fmaf(x[lane + d * 32], ce[lane + d * 32], p);
#pragma unroll
            for (int o = 16; o > 0; o >>= 1)
                p += __shfl_xor_sync(0xFFFFFFFFu, p, o);
            float s = fmaf(-2.0f, p, g_c2[col]);
            if (s < bv || (s == bv && col < bi)) { bv = s; bi = col; }
        }
        if (lane == 0) out[row] = (float)bi;
    }
}

// ============================================================================
extern "C" void kernel_launch(void* const* d_in, const int* in_sizes, int n_in,
                              void* d_out, int out_size) {
    int n0 = in_sizes[0] / C_DIM;
    int n1 = in_sizes[1] / C_DIM;
    const float* X; const float* Cm; int N, K;
    if (n0 >= n1) { X = (const float*)d_in[0]; N = n0;
                    Cm = (const float*)d_in[1]; K = n1; }
    else          { X = (const float*)d_in[1]; N = n1;
                    Cm = (const float*)d_in[0]; K = n0; }
    if (N > N_CAP) N = N_CAP;
    if (K > K_CAP) K = K_CAP;
    float* out = (float*)d_out;

    cudaFuncSetAttribute(assign_mma,
                         cudaFuncAttributeMaxDynamicSharedMemorySize,
                         SMEM_TOTAL);

    // 1) quantize X to int8 (per-row scale) + flag counter reset
    convx8_kernel<<<(N + 7) / 8, 256>>>(X, N);
    // 2) centroid exact norms + int8 quantization
    c2s_kernel<<<(K * 32 + 255) / 256, 256>>>(Cm, K);
    // 3) int8 tensor-core GEMM + fused argmin (top-4 hot loop, top-8 merge)
    assign_mma<<<N / 128, NTHREADS, SMEM_TOTAL>>>(out, K);
    // 4) exact fp32 refinement of near-tie rows (wide grid: latency-bound)
    refine_kernel<<<2048, 256>>>(X, Cm, out);
}